// round 16
// baseline (speedup 1.0000x reference)
#include <cuda_runtime.h>
#include <cuda_fp16.h>
#include <cstdint>

// Problem constants: B=1, C=32, S=20, K=5 (125 taps), offset conv out = 375 ch.
#define NV   8000     // 20^3 voxels
#define NC   32       // channels
#define MOUT 375      // 3*K3 offset channels
#define MPAD 384      // padded to 2 x 192 n-tiles

// Scratch (static device globals — no allocation APIs allowed)
__device__ __align__(16) float g_offv[NV * 384];   // offsets, [v][o] (padded)
__device__ __align__(16) float g_xt[NV * NC];      // x transposed to [v][c]
__device__ __align__(16) float g_attn1[NV * NC];   // deform output, [v][c]
__device__ __align__(16) float g_wdwt[125 * NC];   // w_dw transposed [t][c]
__device__ __align__(16) float g_wspt[343 * NC];   // w_sp transposed [t][c]
// fp16-split operands for the HMMA offset GEMM
__device__ __align__(16) __half g_A[125 * MPAD * 64];   // per tap: [m][wh c0..31 | pad]
__device__ __align__(16) __half g_xpair[NV * 64];       // per voxel: [xh c0..31 | xl c0..31]

__device__ __forceinline__ uint32_t smem_u32(const void* p) {
    uint32_t a;
    asm("{ .reg .u64 t; cvta.to.shared.u64 t, %1; cvt.u32.u64 %0, t; }" : "=r"(a) : "l"(p));
    return a;
}
__device__ __forceinline__ uint32_t sw128(uint32_t off) { return off ^ ((off >> 3) & 0x70); }

// cp.async 16B with zero-fill predication (src-size = 0 skips the read)
__device__ __forceinline__ void cp16(uint32_t dst, const void* src, bool pred) {
    int sz = pred ? 16 : 0;
    asm volatile("cp.async.cg.shared.global [%0], [%1], 16, %2;" :: "r"(dst), "l"(src), "r"(sz));
}
#define CP_COMMIT() asm volatile("cp.async.commit_group;" ::: "memory")
#define CP_WAIT(N)  asm volatile("cp.async.wait_group %0;" :: "n"(N) : "memory")

__device__ __forceinline__ void ldsm_x4(uint32_t& r0, uint32_t& r1, uint32_t& r2,
                                        uint32_t& r3, uint32_t addr) {
    asm volatile("ldmatrix.sync.aligned.m8n8.x4.shared.b16 {%0,%1,%2,%3}, [%4];"
                 : "=r"(r0), "=r"(r1), "=r"(r2), "=r"(r3) : "r"(addr));
}
__device__ __forceinline__ void mma16816(float* c, const uint32_t* a, const uint32_t* b) {
    asm volatile("mma.sync.aligned.m16n8k16.row.col.f32.f16.f16.f32 "
                 "{%0,%1,%2,%3}, {%4,%5,%6,%7}, {%8,%9}, {%0,%1,%2,%3};"
                 : "+f"(c[0]), "+f"(c[1]), "+f"(c[2]), "+f"(c[3])
                 : "r"(a[0]), "r"(a[1]), "r"(a[2]), "r"(a[3]), "r"(b[0]), "r"(b[1]));
}

// ---------------------------------------------------------------------------
// Prep: transposes + fp16 hi/lo split of x ([v][xh c|xl c])
// ---------------------------------------------------------------------------
__global__ __launch_bounds__(256) void prep_kernel(const float* __restrict__ x,
                                                   const float* __restrict__ w_dw,
                                                   const float* __restrict__ w_sp) {
    int idx = blockIdx.x * blockDim.x + threadIdx.x;
    if (idx < NV * 64) {  // g_xpair
        int v = idx >> 6, j = idx & 63, c = j & 31;
        float val = x[c * NV + v];
        __half hi = __float2half(val);
        g_xpair[idx] = (j < 32) ? hi : __float2half(val - __half2float(hi));
    }
    if (idx < NV * NC) {
        int v = idx >> 5, c = idx & 31;
        g_xt[idx] = x[c * NV + v];
    }
    if (idx < 125 * NC) {
        int t = idx >> 5, c = idx & 31;
        g_wdwt[idx] = w_dw[c * 125 + t];
    }
    if (idx < 343 * NC) {
        int t = idx >> 5, c = idx & 31;
        g_wspt[idx] = w_sp[c * 343 + t];
    }
}

// Prep A (coalesced): one block per output row m. Only wh is stored.
__global__ __launch_bounds__(256) void prep_a_kernel(const float* __restrict__ w_off) {
    __shared__ float row[4000];
    const int m = blockIdx.x;
    const int tid = threadIdx.x;
    const bool mok = m < MOUT;
    if (mok)
        for (int i = tid; i < 4000; i += 256) row[i] = w_off[m * 4000 + i];
    __syncthreads();
    const int lane = tid & 31;
    const int wq = tid >> 5;
    for (int t = wq; t < 125; t += 8) {
        float wv = mok ? row[lane * 125 + t] : 0.f;
        size_t base = ((size_t)t * MPAD + m) * 64;
        g_A[base + lane] = __float2half(wv);
    }
}

// ---------------------------------------------------------------------------
// Stage A: offset conv as 125 tap-GEMMs via mma.sync fp16 (2-product split).
// 3-stage cp.async pipeline, ONE __syncthreads per tap. (unchanged)
// ---------------------------------------------------------------------------
#define W_ST  24576
#define X_ST  16384
#define XS_BASE (3 * W_ST)                  // 73728
#define SMEM_SZ (XS_BASE + 3 * X_ST)        // 122880

__global__ __launch_bounds__(256, 1) void gemm_off_kernel(const float* __restrict__ b_off) {
    extern __shared__ __align__(1024) char smem[];
    const uint32_t sb = smem_u32(smem);
    const int tid = threadIdx.x;
    const int lane = tid & 31;
    const int w = tid >> 5;
    const int wm = w & 1;          // m half (64 voxels)
    const int wn = w >> 1;         // n quarter (48 ch)
    const int v0 = blockIdx.x * 128;
    const int n0c = blockIdx.y * 192;

    const int bn = tid >> 1;             // row 0..127
    const int bh = (tid & 1) * 4;        // 16B-chunk base
    const int vq = v0 + bn;
    const bool vok = vq < NV;
    const int vz = vq / 400, vy = (vq / 20) % 20, vx = vq % 20;
    const char* __restrict__ xpB = (const char*)g_xpair;
    const char* __restrict__ gAB = (const char*)g_A;

    auto load_tap = [&](int t, int s) {
        const uint32_t wb = sb + s * W_ST;
        const char* wsrc = gAB + (size_t)(t * MPAD + n0c) * 128;
#pragma unroll
        for (int i = 0; i < 3; i++) {
            int chunk = tid + (i << 8);            // 0..767
            int row = chunk >> 2, cb = (chunk & 3) << 4;
            cp16(wb + sw128((row << 7) + cb), wsrc + (row << 7) + cb, true);
        }
        const uint32_t xb = sb + XS_BASE + s * X_ST;
        const int dz = t / 25 - 2, dy = (t / 5) % 5 - 2, dx = t % 5 - 2;
        const bool valid = vok && ((unsigned)(vz + dz) < 20u) &&
                           ((unsigned)(vy + dy) < 20u) && ((unsigned)(vx + dx) < 20u);
        const int vsrc = valid ? (vq + dz * 400 + dy * 20 + dx) : 0;
        const char* xsrc = xpB + (size_t)vsrc * 128;
#pragma unroll
        for (int i = 0; i < 4; i++) {
            int cb = (bh + i) << 4;
            cp16(xb + sw128((bn << 7) + cb), xsrc + cb, valid);
        }
    };

    float acc[4][6][4];
#pragma unroll
    for (int mf = 0; mf < 4; mf++)
#pragma unroll
        for (int nf = 0; nf < 6; nf++)
#pragma unroll
            for (int q = 0; q < 4; q++) acc[mf][nf][q] = 0.f;

    const int x_row = wm * 64 + (lane & 15);
    const int x_hi16 = (lane >> 4) << 4;
    const int w_row4 = wn * 48 + ((lane >> 4) << 3) + (lane & 7);
    const int w_k16 = ((lane >> 3) & 1) << 4;

    auto loadA = [&](uint32_t (*f)[4], uint32_t xb, int xoff) {
#pragma unroll
        for (int mf = 0; mf < 4; mf++)
            ldsm_x4(f[mf][0], f[mf][1], f[mf][2], f[mf][3],
                    xb + sw128(((x_row + mf * 16) << 7) + xoff + x_hi16));
    };
    auto loadB = [&](uint32_t (*f)[2], uint32_t wb, int woff) {
#pragma unroll
        for (int p = 0; p < 3; p++) {
            uint32_t r0, r1, r2, r3;
            ldsm_x4(r0, r1, r2, r3,
                    wb + sw128(((w_row4 + p * 16) << 7) + woff + w_k16));
            f[2 * p][0] = r0;     f[2 * p][1] = r1;
            f[2 * p + 1][0] = r2; f[2 * p + 1][1] = r3;
        }
    };
    auto mmaSeg = [&](uint32_t (*a)[4], uint32_t (*b)[2]) {
#pragma unroll
        for (int mf = 0; mf < 4; mf++)
#pragma unroll
            for (int nf = 0; nf < 6; nf++)
                mma16816(acc[mf][nf], a[mf], b[nf]);
    };

    load_tap(0, 0); CP_COMMIT();
    load_tap(1, 1); CP_COMMIT();

    for (int t = 0; t < 125; t++) {
        const int s = t % 3;
        CP_WAIT(1);
        __syncthreads();
        if (t < 123) { load_tap(t + 2, (t + 2) % 3); CP_COMMIT(); }

        const uint32_t xb = sb + XS_BASE + s * X_ST;
        const uint32_t wb = sb + s * W_ST;
        uint32_t A[4][4], B[6][2];
        loadB(B, wb, 0);
        loadA(A, xb, 0);   mmaSeg(A, B);   // xh0 * wh0
        loadA(A, xb, 64);  mmaSeg(A, B);   // xl0 * wh0
        loadB(B, wb, 32);
        loadA(A, xb, 32);  mmaSeg(A, B);   // xh1 * wh1
        loadA(A, xb, 96);  mmaSeg(A, B);   // xl1 * wh1
    }

    const int vr = v0 + wm * 64 + (lane >> 2);
    const int ob = n0c + wn * 48 + (lane & 3) * 2;
#pragma unroll
    for (int nf = 0; nf < 6; nf++) {
        int o = ob + nf * 8;
        float bias0 = (o < MOUT) ? b_off[o] : 0.f;
        float bias1 = (o + 1 < MOUT) ? b_off[o + 1] : 0.f;
#pragma unroll
        for (int mf = 0; mf < 4; mf++) {
            int v1 = vr + mf * 16, v2 = v1 + 8;
            if (v1 < NV) {
                float2 r = {acc[mf][nf][0] + bias0, acc[mf][nf][1] + bias1};
                *(float2*)&g_offv[(size_t)v1 * 384 + o] = r;
            }
            if (v2 < NV) {
                float2 r = {acc[mf][nf][2] + bias0, acc[mf][nf][3] + bias1};
                *(float2*)&g_offv[(size_t)v2 * 384 + o] = r;
            }
        }
    }
}

// ---------------------------------------------------------------------------
// Stage B: deformable depthwise conv, warp-cooperative metadata precompute,
// 4-way tap split. Warp = 1 voxel; lanes = 4 tap-quarters x 8 channel-quads.
// Phase A (per kz-plane): lanes 0-24 compute tap metadata into smem.
// Phase B: pure gather+FMA from metadata (no scalar geometry duplication).
// ---------------------------------------------------------------------------
__global__ __launch_bounds__(128) void deform_kernel(const float* __restrict__ b_dw) {
    __shared__ __align__(16) float s_off[4 * 384];
    __shared__ __align__(16) float s_meta[4][25][16];  // [warp][tap][8w|8addr]
    const int tid = threadIdx.x;
    const int lane = tid & 31;
    const int warp = tid >> 5;             // 0..3
    const int sub = lane & 7;              // channel-quad index
    const int tq = lane >> 3;              // tap-quarter (0..3)
    const int v = blockIdx.x * 4 + warp;

    // stage this warp's voxel offsets (384 floats = 96 float4)
    {
        const float4* src = (const float4*)(g_offv + (size_t)v * 384);
        float4* dst = (float4*)(s_off + warp * 384);
#pragma unroll
        for (int i = 0; i < 3; i++) dst[lane + 32 * i] = src[lane + 32 * i];
    }
    __syncwarp();

    const int vz = v / 400;
    const int vy = (v / 20) % 20;
    const int vx = v % 20;
    const float* __restrict__ off = s_off + warp * 384;
    const float4* __restrict__ xt4 = (const float4*)g_xt;
    const float4* __restrict__ wd4 = (const float4*)g_wdwt;

    float4 acc = {0.f, 0.f, 0.f, 0.f};
#pragma unroll 1
    for (int kz = 0; kz < 5; kz++) {
        // ---- Phase A: metadata for 25 taps of this kz plane ----
        if (lane < 25) {
            int r = lane;
            int ky = r / 5, kx = r - ky * 5;
            int t = kz * 25 + r;
            float pd = (float)(vz + kz - 2) + off[t * 3 + 0];
            float ph = (float)(vy + ky - 2) + off[t * 3 + 1];
            float pw = (float)(vx + kx - 2) + off[t * 3 + 2];
            float d0f = floorf(pd), h0f = floorf(ph), w0f = floorf(pw);
            float fd = pd - d0f, fh = ph - h0f, fw = pw - w0f;
            int d0 = (int)d0f, h0 = (int)h0f, w0 = (int)w0f;
            float wz0 = ((unsigned)d0       < 20u) ? (1.f - fd) : 0.f;
            float wz1 = ((unsigned)(d0 + 1) < 20u) ? fd         : 0.f;
            float wy0 = ((unsigned)h0       < 20u) ? (1.f - fh) : 0.f;
            float wy1 = ((unsigned)(h0 + 1) < 20u) ? fh         : 0.f;
            float wx0 = ((unsigned)w0       < 20u) ? (1.f - fw) : 0.f;
            float wx1 = ((unsigned)(w0 + 1) < 20u) ? fw         : 0.f;
            int iz0 = min(max(d0, 0), 19),     iz1 = min(max(d0 + 1, 0), 19);
            int iy0 = min(max(h0, 0), 19),     iy1 = min(max(h0 + 1, 0), 19);
            int ix0 = min(max(w0, 0), 19),     ix1 = min(max(w0 + 1, 0), 19);
            int z0 = iz0 * 400, z1 = iz1 * 400;
            int y0 = iy0 * 20,  y1 = iy1 * 20;
            int r00 = z0 + y0, r01 = z0 + y1, r10 = z1 + y0, r11 = z1 + y1;
            float w00 = wz0 * wy0, w01 = wz0 * wy1, w10 = wz1 * wy0, w11 = wz1 * wy1;
            float* m = s_meta[warp][r];
            float4 wv0 = {w00 * wx0, w00 * wx1, w01 * wx0, w01 * wx1};
            float4 wv1 = {w10 * wx0, w10 * wx1, w11 * wx0, w11 * wx1};
            *(float4*)(m)     = wv0;
            *(float4*)(m + 4) = wv1;
            int4 a0 = {(r00 + ix0) * 8, (r00 + ix1) * 8, (r01 + ix0) * 8, (r01 + ix1) * 8};
            int4 a1 = {(r10 + ix0) * 8, (r10 + ix1) * 8, (r11 + ix0) * 8, (r11 + ix1) * 8};
            *(int4*)(m + 8)  = a0;
            *(int4*)(m + 12) = a1;
        }
        __syncwarp();
        // ---- Phase B: gather + FMA from metadata (taps split 4-way) ----
#pragma unroll 1
        for (int r = tq; r < 25; r += 4) {
            const float* m = s_meta[warp][r];
            float4 wv0 = *(const float4*)(m);
            float4 wv1 = *(const float4*)(m + 4);
            int4 a0 = *(const int4*)(m + 8);
            int4 a1 = *(const int4*)(m + 12);
            float4 x0 = xt4[a0.x + sub];
            float4 x1 = xt4[a0.y + sub];
            float4 x2 = xt4[a0.z + sub];
            float4 x3 = xt4[a0.w + sub];
            float4 x4 = xt4[a1.x + sub];
            float4 x5 = xt4[a1.y + sub];
            float4 x6 = xt4[a1.z + sub];
            float4 x7 = xt4[a1.w + sub];
            float4 s;
            s.x = wv0.x*x0.x + wv0.y*x1.x + wv0.z*x2.x + wv0.w*x3.x +
                  wv1.x*x4.x + wv1.y*x5.x + wv1.z*x6.x + wv1.w*x7.x;
            s.y = wv0.x*x0.y + wv0.y*x1.y + wv0.z*x2.y + wv0.w*x3.y +
                  wv1.x*x4.y + wv1.y*x5.y + wv1.z*x6.y + wv1.w*x7.y;
            s.z = wv0.x*x0.z + wv0.y*x1.z + wv0.z*x2.z + wv0.w*x3.z +
                  wv1.x*x4.z + wv1.y*x5.z + wv1.z*x6.z + wv1.w*x7.z;
            s.w = wv0.x*x0.w + wv0.y*x1.w + wv0.z*x2.w + wv0.w*x3.w +
                  wv1.x*x4.w + wv1.y*x5.w + wv1.z*x6.w + wv1.w*x7.w;
            float4 wt = wd4[(kz * 25 + r) * 8 + sub];
            acc.x += wt.x * s.x;
            acc.y += wt.y * s.y;
            acc.z += wt.z * s.z;
            acc.w += wt.w * s.w;
        }
        __syncwarp();
    }
    // combine tap quarters
    acc.x += __shfl_xor_sync(0xffffffffu, acc.x, 8);
    acc.y += __shfl_xor_sync(0xffffffffu, acc.y, 8);
    acc.z += __shfl_xor_sync(0xffffffffu, acc.z, 8);
    acc.w += __shfl_xor_sync(0xffffffffu, acc.w, 8);
    acc.x += __shfl_xor_sync(0xffffffffu, acc.x, 16);
    acc.y += __shfl_xor_sync(0xffffffffu, acc.y, 16);
    acc.z += __shfl_xor_sync(0xffffffffu, acc.z, 16);
    acc.w += __shfl_xor_sync(0xffffffffu, acc.w, 16);
    if (tq == 0) {
        float4 bias = ((const float4*)b_dw)[sub];
        acc.x += bias.x; acc.y += bias.y; acc.z += bias.z; acc.w += bias.w;
        ((float4*)g_attn1)[v * 8 + sub] = acc;
    }
}

// ---------------------------------------------------------------------------
// Stage C+D fused: dilated 7x7x7 depthwise conv -> smem -> 32x32 pointwise
// (+bias) -> x*attn, NCDHW output. No g_attn2 global round-trip.
// ---------------------------------------------------------------------------
__global__ __launch_bounds__(128) void spconv_pw_kernel(const float* __restrict__ b_sp,
                                                        const float* __restrict__ w_pw,
                                                        const float* __restrict__ b_pw,
                                                        const float* __restrict__ x,
                                                        float* __restrict__ out) {
    __shared__ float s_attn[8][33];
    const int tid = threadIdx.x;
    const int lane = tid & 31;
    const int warp = tid >> 5;
    const int sub = lane & 7;
    const int qv = (lane >> 3) & 1;
    const int th = lane >> 4;
    const int vloc = warp * 2 + qv;
    const int v = blockIdx.x * 8 + vloc;
    const int vz = v / 400;
    const int vy = (v / 20) % 20;
    const int vx = v % 20;
    const float4* __restrict__ a4 = (const float4*)g_attn1;
    const float4* __restrict__ w4 = (const float4*)g_wspt;

    float4 acc = {0.f, 0.f, 0.f, 0.f};
#pragma unroll 1
    for (int row = th; row < 49; row += 2) {
        const int kz = row / 7;
        const int ky = row - kz * 7;
        int zi = vz + kz * 3 - 9;
        if ((unsigned)zi >= 20u) continue;
        int yi = vy + ky * 3 - 9;
        if ((unsigned)yi >= 20u) continue;
        int rowbase = (zi * 20 + yi) * 20;
        int tbase = row * 7;
#pragma unroll
        for (int kx = 0; kx < 7; kx++) {
            int xi = vx + kx * 3 - 9;
            if ((unsigned)xi < 20u) {
                float4 wv = w4[(tbase + kx) * 8 + sub];
                float4 av = a4[(rowbase + xi) * 8 + sub];
                acc.x += wv.x * av.x;
                acc.y += wv.y * av.y;
                acc.z += wv.z * av.z;
                acc.w += wv.w * av.w;
            }
        }
    }
    acc.x += __shfl_xor_sync(0xffffffffu, acc.x, 16);
    acc.y += __shfl_xor_sync(0xffffffffu, acc.y, 16);
    acc.z += __shfl_xor_sync(0xffffffffu, acc.z, 16);
    acc.w += __shfl_xor_sync(0xffffffffu, acc.w, 16);
    if (th == 0) {
        float4 bias = ((const float4*)b_sp)[sub];
        s_attn[vloc][sub * 4 + 0] = acc.x + bias.x;
        s_attn[vloc][sub * 4 + 1] = acc.y + bias.y;
        s_attn[vloc][sub * 4 + 2] = acc.z + bias.z;
        s_attn[vloc][sub * 4 + 3] = acc.w + bias.w;
    }
    __syncthreads();

    // pointwise: 8 voxels x 32 out-ch = 256 outputs, 2 per thread
    const int pv = tid >> 4;               // voxel 0..7
    const int o0 = (tid & 15) * 2;
    const int gv = blockIdx.x * 8 + pv;
    const float* arow = s_attn[pv];
#pragma unroll
    for (int k = 0; k < 2; k++) {
        int o = o0 + k;
        float a = b_pw[o];
        const float* wrow = w_pw + o * 32;
#pragma unroll
        for (int c = 0; c < 32; c++) a += wrow[c] * arow[c];
        out[o * NV + gv] = x[o * NV + gv] * a;
    }
}

// ---------------------------------------------------------------------------
extern "C" void kernel_launch(void* const* d_in, const int* in_sizes, int n_in,
                              void* d_out, int out_size) {
    const float* x     = (const float*)d_in[0];
    const float* w_off = (const float*)d_in[1];
    const float* b_off = (const float*)d_in[2];
    const float* w_dw  = (const float*)d_in[3];
    const float* b_dw  = (const float*)d_in[4];
    const float* w_sp  = (const float*)d_in[5];
    const float* b_sp  = (const float*)d_in[6];
    const float* w_pw  = (const float*)d_in[7];
    const float* b_pw  = (const float*)d_in[8];
    float* out = (float*)d_out;

    cudaFuncSetAttribute(gemm_off_kernel,
                         cudaFuncAttributeMaxDynamicSharedMemorySize, SMEM_SZ);

    prep_kernel<<<2000, 256>>>(x, w_dw, w_sp);
    prep_a_kernel<<<MPAD, 256>>>(w_off);               // 1 block per out-row
    dim3 gg(63, 2);                                    // 63 v-tiles x 2 n-tiles
    gemm_off_kernel<<<gg, 256, SMEM_SZ>>>(b_off);
    deform_kernel<<<2000, 128>>>(b_dw);
    spconv_pw_kernel<<<1000, 128>>>(b_sp, w_pw, b_pw, x, out);
}

// round 17
// speedup vs baseline: 1.1975x; 1.1975x over previous
#include <cuda_runtime.h>
#include <cuda_fp16.h>
#include <cstdint>

// Problem constants: B=1, C=32, S=20, K=5 (125 taps), offset conv out = 375 ch.
#define NV   8000     // 20^3 voxels
#define NC   32       // channels
#define MOUT 375      // 3*K3 offset channels
#define MPAD 384      // padded to 2 x 192 n-tiles

// Scratch (static device globals — no allocation APIs allowed)
__device__ __align__(16) float g_offv[NV * 384];   // offsets, [v][o] (padded)
__device__ __align__(16) float g_xt[NV * NC];      // x transposed to [v][c]
__device__ __align__(16) float g_attn1[NV * NC];   // deform output, [v][c]
__device__ __align__(16) float g_attn2[NV * NC];   // dilated depthwise output, [v][c]
__device__ __align__(16) float g_wdwt[125 * NC];   // w_dw transposed [t][c]
__device__ __align__(16) float g_wspt[343 * NC];   // w_sp transposed [t][c]
// fp16-split operands for the HMMA offset GEMM; hi half doubles as deform's
// fp16 sample source ([v][xh c0..31 | xl c0..31])
__device__ __align__(16) __half g_A[125 * MPAD * 64];   // per tap: [m][wh c0..31 | pad]
__device__ __align__(16) __half g_xpair[NV * 64];

__device__ __forceinline__ uint32_t smem_u32(const void* p) {
    uint32_t a;
    asm("{ .reg .u64 t; cvta.to.shared.u64 t, %1; cvt.u32.u64 %0, t; }" : "=r"(a) : "l"(p));
    return a;
}
__device__ __forceinline__ uint32_t sw128(uint32_t off) { return off ^ ((off >> 3) & 0x70); }

// cp.async 16B with zero-fill predication (src-size = 0 skips the read)
__device__ __forceinline__ void cp16(uint32_t dst, const void* src, bool pred) {
    int sz = pred ? 16 : 0;
    asm volatile("cp.async.cg.shared.global [%0], [%1], 16, %2;" :: "r"(dst), "l"(src), "r"(sz));
}
#define CP_COMMIT() asm volatile("cp.async.commit_group;" ::: "memory")
#define CP_WAIT(N)  asm volatile("cp.async.wait_group %0;" :: "n"(N) : "memory")

__device__ __forceinline__ void ldsm_x4(uint32_t& r0, uint32_t& r1, uint32_t& r2,
                                        uint32_t& r3, uint32_t addr) {
    asm volatile("ldmatrix.sync.aligned.m8n8.x4.shared.b16 {%0,%1,%2,%3}, [%4];"
                 : "=r"(r0), "=r"(r1), "=r"(r2), "=r"(r3) : "r"(addr));
}
__device__ __forceinline__ void mma16816(float* c, const uint32_t* a, const uint32_t* b) {
    asm volatile("mma.sync.aligned.m16n8k16.row.col.f32.f16.f16.f32 "
                 "{%0,%1,%2,%3}, {%4,%5,%6,%7}, {%8,%9}, {%0,%1,%2,%3};"
                 : "+f"(c[0]), "+f"(c[1]), "+f"(c[2]), "+f"(c[3])
                 : "r"(a[0]), "r"(a[1]), "r"(a[2]), "r"(a[3]), "r"(b[0]), "r"(b[1]));
}

// ---------------------------------------------------------------------------
// Prep: transposes + fp16 hi/lo split of x ([v][xh c|xl c])
// ---------------------------------------------------------------------------
__global__ __launch_bounds__(256) void prep_kernel(const float* __restrict__ x,
                                                   const float* __restrict__ w_dw,
                                                   const float* __restrict__ w_sp) {
    int idx = blockIdx.x * blockDim.x + threadIdx.x;
    if (idx < NV * 64) {  // g_xpair
        int v = idx >> 6, j = idx & 63, c = j & 31;
        float val = x[c * NV + v];
        __half hi = __float2half(val);
        g_xpair[idx] = (j < 32) ? hi : __float2half(val - __half2float(hi));
    }
    if (idx < NV * NC) {
        int v = idx >> 5, c = idx & 31;
        g_xt[idx] = x[c * NV + v];
    }
    if (idx < 125 * NC) {
        int t = idx >> 5, c = idx & 31;
        g_wdwt[idx] = w_dw[c * 125 + t];
    }
    if (idx < 343 * NC) {
        int t = idx >> 5, c = idx & 31;
        g_wspt[idx] = w_sp[c * 343 + t];
    }
}

// Prep A (coalesced): one block per output row m. Only wh is stored.
__global__ __launch_bounds__(256) void prep_a_kernel(const float* __restrict__ w_off) {
    __shared__ float row[4000];
    const int m = blockIdx.x;
    const int tid = threadIdx.x;
    const bool mok = m < MOUT;
    if (mok)
        for (int i = tid; i < 4000; i += 256) row[i] = w_off[m * 4000 + i];
    __syncthreads();
    const int lane = tid & 31;
    const int wq = tid >> 5;
    for (int t = wq; t < 125; t += 8) {
        float wv = mok ? row[lane * 125 + t] : 0.f;
        size_t base = ((size_t)t * MPAD + m) * 64;
        g_A[base + lane] = __float2half(wv);
    }
}

// ---------------------------------------------------------------------------
// Stage A: offset conv as 125 tap-GEMMs via mma.sync fp16 (2-product split).
// 3-stage cp.async pipeline, ONE __syncthreads per tap. (unchanged from R13)
// ---------------------------------------------------------------------------
#define W_ST  24576
#define X_ST  16384
#define XS_BASE (3 * W_ST)                  // 73728
#define SMEM_SZ (XS_BASE + 3 * X_ST)        // 122880

__global__ __launch_bounds__(256, 1) void gemm_off_kernel(const float* __restrict__ b_off) {
    extern __shared__ __align__(1024) char smem[];
    const uint32_t sb = smem_u32(smem);
    const int tid = threadIdx.x;
    const int lane = tid & 31;
    const int w = tid >> 5;
    const int wm = w & 1;          // m half (64 voxels)
    const int wn = w >> 1;         // n quarter (48 ch)
    const int v0 = blockIdx.x * 128;
    const int n0c = blockIdx.y * 192;

    const int bn = tid >> 1;             // row 0..127
    const int bh = (tid & 1) * 4;        // 16B-chunk base
    const int vq = v0 + bn;
    const bool vok = vq < NV;
    const int vz = vq / 400, vy = (vq / 20) % 20, vx = vq % 20;
    const char* __restrict__ xpB = (const char*)g_xpair;
    const char* __restrict__ gAB = (const char*)g_A;

    auto load_tap = [&](int t, int s) {
        const uint32_t wb = sb + s * W_ST;
        const char* wsrc = gAB + (size_t)(t * MPAD + n0c) * 128;
#pragma unroll
        for (int i = 0; i < 3; i++) {
            int chunk = tid + (i << 8);            // 0..767
            int row = chunk >> 2, cb = (chunk & 3) << 4;
            cp16(wb + sw128((row << 7) + cb), wsrc + (row << 7) + cb, true);
        }
        const uint32_t xb = sb + XS_BASE + s * X_ST;
        const int dz = t / 25 - 2, dy = (t / 5) % 5 - 2, dx = t % 5 - 2;
        const bool valid = vok && ((unsigned)(vz + dz) < 20u) &&
                           ((unsigned)(vy + dy) < 20u) && ((unsigned)(vx + dx) < 20u);
        const int vsrc = valid ? (vq + dz * 400 + dy * 20 + dx) : 0;
        const char* xsrc = xpB + (size_t)vsrc * 128;
#pragma unroll
        for (int i = 0; i < 4; i++) {
            int cb = (bh + i) << 4;
            cp16(xb + sw128((bn << 7) + cb), xsrc + cb, valid);
        }
    };

    float acc[4][6][4];
#pragma unroll
    for (int mf = 0; mf < 4; mf++)
#pragma unroll
        for (int nf = 0; nf < 6; nf++)
#pragma unroll
            for (int q = 0; q < 4; q++) acc[mf][nf][q] = 0.f;

    const int x_row = wm * 64 + (lane & 15);
    const int x_hi16 = (lane >> 4) << 4;
    const int w_row4 = wn * 48 + ((lane >> 4) << 3) + (lane & 7);
    const int w_k16 = ((lane >> 3) & 1) << 4;

    auto loadA = [&](uint32_t (*f)[4], uint32_t xb, int xoff) {
#pragma unroll
        for (int mf = 0; mf < 4; mf++)
            ldsm_x4(f[mf][0], f[mf][1], f[mf][2], f[mf][3],
                    xb + sw128(((x_row + mf * 16) << 7) + xoff + x_hi16));
    };
    auto loadB = [&](uint32_t (*f)[2], uint32_t wb, int woff) {
#pragma unroll
        for (int p = 0; p < 3; p++) {
            uint32_t r0, r1, r2, r3;
            ldsm_x4(r0, r1, r2, r3,
                    wb + sw128(((w_row4 + p * 16) << 7) + woff + w_k16));
            f[2 * p][0] = r0;     f[2 * p][1] = r1;
            f[2 * p + 1][0] = r2; f[2 * p + 1][1] = r3;
        }
    };
    auto mmaSeg = [&](uint32_t (*a)[4], uint32_t (*b)[2]) {
#pragma unroll
        for (int mf = 0; mf < 4; mf++)
#pragma unroll
            for (int nf = 0; nf < 6; nf++)
                mma16816(acc[mf][nf], a[mf], b[nf]);
    };

    load_tap(0, 0); CP_COMMIT();
    load_tap(1, 1); CP_COMMIT();

    for (int t = 0; t < 125; t++) {
        const int s = t % 3;
        CP_WAIT(1);
        __syncthreads();
        if (t < 123) { load_tap(t + 2, (t + 2) % 3); CP_COMMIT(); }

        const uint32_t xb = sb + XS_BASE + s * X_ST;
        const uint32_t wb = sb + s * W_ST;
        uint32_t A[4][4], B[6][2];
        loadB(B, wb, 0);
        loadA(A, xb, 0);   mmaSeg(A, B);   // xh0 * wh0
        loadA(A, xb, 64);  mmaSeg(A, B);   // xl0 * wh0
        loadB(B, wb, 32);
        loadA(A, xb, 32);  mmaSeg(A, B);   // xh1 * wh1
        loadA(A, xb, 96);  mmaSeg(A, B);   // xl1 * wh1
    }

    const int vr = v0 + wm * 64 + (lane >> 2);
    const int ob = n0c + wn * 48 + (lane & 3) * 2;
#pragma unroll
    for (int nf = 0; nf < 6; nf++) {
        int o = ob + nf * 8;
        float bias0 = (o < MOUT) ? b_off[o] : 0.f;
        float bias1 = (o + 1 < MOUT) ? b_off[o + 1] : 0.f;
#pragma unroll
        for (int mf = 0; mf < 4; mf++) {
            int v1 = vr + mf * 16, v2 = v1 + 8;
            if (v1 < NV) {
                float2 r = {acc[mf][nf][0] + bias0, acc[mf][nf][1] + bias1};
                *(float2*)&g_offv[(size_t)v1 * 384 + o] = r;
            }
            if (v2 < NV) {
                float2 r = {acc[mf][nf][2] + bias0, acc[mf][nf][3] + bias1};
                *(float2*)&g_offv[(size_t)v2 * 384 + o] = r;
            }
        }
    }
}

// ---------------------------------------------------------------------------
// Stage B: deformable depthwise conv, warp-cooperative metadata precompute
// (R14 structure: warp = 2 voxels x 2 tap-halves). Gathers read fp16 x from
// g_xpair's hi half (64B/corner line vs 128B) -> halved L1 traffic.
// ---------------------------------------------------------------------------
__global__ __launch_bounds__(128) void deform_kernel(const float* __restrict__ b_dw) {
    __shared__ __align__(16) float s_off[8 * 384];
    __shared__ __align__(16) float s_meta[4][50][16];  // [warp][inst][8w|8byteoff]
    const int tid = threadIdx.x;
    const int lane = tid & 31;
    const int warp = tid >> 5;             // 0..3
    const int sub = lane & 7;              // channel-quad index
    const int qv = (lane >> 3) & 1;        // voxel within warp (0..1)
    const int th = lane >> 4;              // tap-half (0..1)
    const int vbase = blockIdx.x * 8;

    // stage this warp's 2 voxels of offsets (768 floats = 192 float4)
    {
        const float4* src = (const float4*)(g_offv + (size_t)(vbase + warp * 2) * 384);
        float4* dst = (float4*)(s_off + warp * 2 * 384);
#pragma unroll
        for (int i = 0; i < 6; i++) dst[lane + 32 * i] = src[lane + 32 * i];
    }
    __syncwarp();

    const int v = vbase + warp * 2 + qv;
    const char* __restrict__ xp = (const char*)g_xpair;
    const float4* __restrict__ wd4 = (const float4*)g_wdwt;

    float4 acc = {0.f, 0.f, 0.f, 0.f};
#pragma unroll 1
    for (int kz = 0; kz < 5; kz++) {
        // ---- Phase A: metadata for 50 instances (2 vox x 25 taps) ----
#pragma unroll
        for (int ii = 0; ii < 2; ii++) {
            int inst = lane + 32 * ii;
            if (inst < 50) {
                int aqv = (inst >= 25) ? 1 : 0;
                int r = inst - aqv * 25;
                int av = vbase + warp * 2 + aqv;
                int avz = av / 400, avy = (av / 20) % 20, avx = av % 20;
                const float* aoff = s_off + (warp * 2 + aqv) * 384;
                int ky = r / 5, kx = r - ky * 5;
                int t = kz * 25 + r;
                float pd = (float)(avz + kz - 2) + aoff[t * 3 + 0];
                float ph = (float)(avy + ky - 2) + aoff[t * 3 + 1];
                float pw = (float)(avx + kx - 2) + aoff[t * 3 + 2];
                float d0f = floorf(pd), h0f = floorf(ph), w0f = floorf(pw);
                float fd = pd - d0f, fh = ph - h0f, fw = pw - w0f;
                int d0 = (int)d0f, h0 = (int)h0f, w0 = (int)w0f;
                float wz0 = ((unsigned)d0       < 20u) ? (1.f - fd) : 0.f;
                float wz1 = ((unsigned)(d0 + 1) < 20u) ? fd         : 0.f;
                float wy0 = ((unsigned)h0       < 20u) ? (1.f - fh) : 0.f;
                float wy1 = ((unsigned)(h0 + 1) < 20u) ? fh         : 0.f;
                float wx0 = ((unsigned)w0       < 20u) ? (1.f - fw) : 0.f;
                float wx1 = ((unsigned)(w0 + 1) < 20u) ? fw         : 0.f;
                int iz0 = min(max(d0, 0), 19),     iz1 = min(max(d0 + 1, 0), 19);
                int iy0 = min(max(h0, 0), 19),     iy1 = min(max(h0 + 1, 0), 19);
                int ix0 = min(max(w0, 0), 19),     ix1 = min(max(w0 + 1, 0), 19);
                int z0 = iz0 * 400, z1 = iz1 * 400;
                int y0 = iy0 * 20,  y1 = iy1 * 20;
                int r00 = z0 + y0, r01 = z0 + y1, r10 = z1 + y0, r11 = z1 + y1;
                float w00 = wz0 * wy0, w01 = wz0 * wy1, w10 = wz1 * wy0, w11 = wz1 * wy1;
                float* m = s_meta[warp][inst];
                float4 wv0 = {w00 * wx0, w00 * wx1, w01 * wx0, w01 * wx1};
                float4 wv1 = {w10 * wx0, w10 * wx1, w11 * wx0, w11 * wx1};
                *(float4*)(m)     = wv0;
                *(float4*)(m + 4) = wv1;
                // byte offsets into g_xpair (128B per voxel row; hi half used)
                int4 a0 = {(r00 + ix0) << 7, (r00 + ix1) << 7, (r01 + ix0) << 7, (r01 + ix1) << 7};
                int4 a1 = {(r10 + ix0) << 7, (r10 + ix1) << 7, (r11 + ix0) << 7, (r11 + ix1) << 7};
                *(int4*)(m + 8)  = a0;
                *(int4*)(m + 12) = a1;
            }
        }
        __syncwarp();
        // ---- Phase B: fp16 gather + convert + FMA from metadata ----
        const int sb8 = sub * 8;   // byte offset of this lane's 4 channels
#pragma unroll 1
        for (int r = th; r < 25; r += 2) {
            const float* m = s_meta[warp][qv * 25 + r];
            float4 wv0 = *(const float4*)(m);
            float4 wv1 = *(const float4*)(m + 4);
            int4 a0 = *(const int4*)(m + 8);
            int4 a1 = *(const int4*)(m + 12);
            uint2 q0 = *(const uint2*)(xp + a0.x + sb8);
            uint2 q1 = *(const uint2*)(xp + a0.y + sb8);
            uint2 q2 = *(const uint2*)(xp + a0.z + sb8);
            uint2 q3 = *(const uint2*)(xp + a0.w + sb8);
            uint2 q4 = *(const uint2*)(xp + a1.x + sb8);
            uint2 q5 = *(const uint2*)(xp + a1.y + sb8);
            uint2 q6 = *(const uint2*)(xp + a1.z + sb8);
            uint2 q7 = *(const uint2*)(xp + a1.w + sb8);
            float2 p0a = __half22float2(*(__half2*)&q0.x), p0b = __half22float2(*(__half2*)&q0.y);
            float2 p1a = __half22float2(*(__half2*)&q1.x), p1b = __half22float2(*(__half2*)&q1.y);
            float2 p2a = __half22float2(*(__half2*)&q2.x), p2b = __half22float2(*(__half2*)&q2.y);
            float2 p3a = __half22float2(*(__half2*)&q3.x), p3b = __half22float2(*(__half2*)&q3.y);
            float2 p4a = __half22float2(*(__half2*)&q4.x), p4b = __half22float2(*(__half2*)&q4.y);
            float2 p5a = __half22float2(*(__half2*)&q5.x), p5b = __half22float2(*(__half2*)&q5.y);
            float2 p6a = __half22float2(*(__half2*)&q6.x), p6b = __half22float2(*(__half2*)&q6.y);
            float2 p7a = __half22float2(*(__half2*)&q7.x), p7b = __half22float2(*(__half2*)&q7.y);
            float4 s;
            s.x = wv0.x*p0a.x + wv0.y*p1a.x + wv0.z*p2a.x + wv0.w*p3a.x +
                  wv1.x*p4a.x + wv1.y*p5a.x + wv1.z*p6a.x + wv1.w*p7a.x;
            s.y = wv0.x*p0a.y + wv0.y*p1a.y + wv0.z*p2a.y + wv0.w*p3a.y +
                  wv1.x*p4a.y + wv1.y*p5a.y + wv1.z*p6a.y + wv1.w*p7a.y;
            s.z = wv0.x*p0b.x + wv0.y*p1b.x + wv0.z*p2b.x + wv0.w*p3b.x +
                  wv1.x*p4b.x + wv1.y*p5b.x + wv1.z*p6b.x + wv1.w*p7b.x;
            s.w = wv0.x*p0b.y + wv0.y*p1b.y + wv0.z*p2b.y + wv0.w*p3b.y +
                  wv1.x*p4b.y + wv1.y*p5b.y + wv1.z*p6b.y + wv1.w*p7b.y;
            float4 wt = wd4[(kz * 25 + r) * 8 + sub];
            acc.x += wt.x * s.x;
            acc.y += wt.y * s.y;
            acc.z += wt.z * s.z;
            acc.w += wt.w * s.w;
        }
        __syncwarp();
    }
    // combine tap halves
    acc.x += __shfl_xor_sync(0xffffffffu, acc.x, 16);
    acc.y += __shfl_xor_sync(0xffffffffu, acc.y, 16);
    acc.z += __shfl_xor_sync(0xffffffffu, acc.z, 16);
    acc.w += __shfl_xor_sync(0xffffffffu, acc.w, 16);
    if (th == 0) {
        float4 bias = ((const float4*)b_dw)[sub];
        acc.x += bias.x; acc.y += bias.y; acc.z += bias.z; acc.w += bias.w;
        ((float4*)g_attn1)[v * 8 + sub] = acc;
    }
}

// ---------------------------------------------------------------------------
// Stage C: dilated (3) 7x7x7 depthwise conv, pad 9. Warp = 2 voxels x
// 2 tap-halves; 8 lanes x 4 channels. (R14, unchanged)
// ---------------------------------------------------------------------------
__global__ __launch_bounds__(128) void spconv_kernel(const float* __restrict__ b_sp) {
    const int lane = threadIdx.x & 31;
    const int sub = lane & 7;
    const int qv = (lane >> 3) & 1;
    const int th = lane >> 4;
    const int v = blockIdx.x * 8 + (threadIdx.x >> 5) * 2 + qv;
    const int vz = v / 400;
    const int vy = (v / 20) % 20;
    const int vx = v % 20;
    const float4* __restrict__ a4 = (const float4*)g_attn1;
    const float4* __restrict__ w4 = (const float4*)g_wspt;

    float4 acc = {0.f, 0.f, 0.f, 0.f};
#pragma unroll 1
    for (int row = th; row < 49; row += 2) {
        const int kz = row / 7;
        const int ky = row - kz * 7;
        int zi = vz + kz * 3 - 9;
        if ((unsigned)zi >= 20u) continue;
        int yi = vy + ky * 3 - 9;
        if ((unsigned)yi >= 20u) continue;
        int rowbase = (zi * 20 + yi) * 20;
        int tbase = row * 7;
#pragma unroll
        for (int kx = 0; kx < 7; kx++) {
            int xi = vx + kx * 3 - 9;
            if ((unsigned)xi < 20u) {
                float4 wv = w4[(tbase + kx) * 8 + sub];
                float4 av = a4[(rowbase + xi) * 8 + sub];
                acc.x += wv.x * av.x;
                acc.y += wv.y * av.y;
                acc.z += wv.z * av.z;
                acc.w += wv.w * av.w;
            }
        }
    }
    acc.x += __shfl_xor_sync(0xffffffffu, acc.x, 16);
    acc.y += __shfl_xor_sync(0xffffffffu, acc.y, 16);
    acc.z += __shfl_xor_sync(0xffffffffu, acc.z, 16);
    acc.w += __shfl_xor_sync(0xffffffffu, acc.w, 16);
    if (th == 0) {
        float4 bias = ((const float4*)b_sp)[sub];
        acc.x += bias.x; acc.y += bias.y; acc.z += bias.z; acc.w += bias.w;
        ((float4*)g_attn2)[v * 8 + sub] = acc;
    }
}

// ---------------------------------------------------------------------------
// Stage D: 32x32 pointwise (+bias) fused with final x*attn, NCDHW output.
// (R14, unchanged)
// ---------------------------------------------------------------------------
__global__ __launch_bounds__(256) void pw_kernel(const float* __restrict__ w_pw,
                                                 const float* __restrict__ b_pw,
                                                 const float* __restrict__ x,
                                                 float* __restrict__ out) {
    __shared__ float a_s[32][33];
    __shared__ float w_s[1024];
    const int tid = threadIdx.x;
    const int v0 = blockIdx.x * 32;
#pragma unroll
    for (int i = 0; i < 4; i++) {
        int e = tid + 256 * i;
        w_s[e] = w_pw[e];
        int vv = e >> 5, cc = e & 31;
        a_s[vv][cc] = g_attn2[v0 * 32 + e];
    }
    __syncthreads();

    const int lane = tid & 31;
    const int wq = tid >> 5;
#pragma unroll
    for (int i = 0; i < 4; i++) {
        int o = wq + 8 * i;
        float acc = b_pw[o];
#pragma unroll
        for (int c = 0; c < 32; c++)
            acc += w_s[o * 32 + c] * a_s[lane][c];
        int v = v0 + lane;
        out[o * NV + v] = x[o * NV + v] * acc;
    }
}

// ---------------------------------------------------------------------------
extern "C" void kernel_launch(void* const* d_in, const int* in_sizes, int n_in,
                              void* d_out, int out_size) {
    const float* x     = (const float*)d_in[0];
    const float* w_off = (const float*)d_in[1];
    const float* b_off = (const float*)d_in[2];
    const float* w_dw  = (const float*)d_in[3];
    const float* b_dw  = (const float*)d_in[4];
    const float* w_sp  = (const float*)d_in[5];
    const float* b_sp  = (const float*)d_in[6];
    const float* w_pw  = (const float*)d_in[7];
    const float* b_pw  = (const float*)d_in[8];
    float* out = (float*)d_out;

    cudaFuncSetAttribute(gemm_off_kernel,
                         cudaFuncAttributeMaxDynamicSharedMemorySize, SMEM_SZ);

    prep_kernel<<<2000, 256>>>(x, w_dw, w_sp);
    prep_a_kernel<<<MPAD, 256>>>(w_off);               // 1 block per out-row
    dim3 gg(63, 2);                                    // 63 v-tiles x 2 n-tiles
    gemm_off_kernel<<<gg, 256, SMEM_SZ>>>(b_off);
    deform_kernel<<<1000, 128>>>(b_dw);
    spconv_kernel<<<1000, 128>>>(b_sp);
    pw_kernel<<<250, 256>>>(w_pw, b_pw, x, out);
}